// round 16
// baseline (speedup 1.0000x reference)
#include <cuda_runtime.h>
#include <cstdint>

// FusionFeature_Layer on GB300 — emulated-fp32 flash attention on mma.sync
// (bf16 hi/lo 3-term split), bf16 prepass + cp.async pipelined tiles.
// R16: warp-specialized. WG0 (warps 0-3): GEMM1 + exp + pack -> P via
// stmatrix. WG1 (warps 4-7): GEMM2 on the previous tile. Register union
// (Q-frags | O-accum) keeps <=128 regs/thread -> 16 warps/SM.
//
//   qf[b,n,c] = query.flat [b*N*C + n*C + c]
//   sf[b,c,m] = support.flat[b*C*N + c*N + m]
//   A = qf @ sf ; attn = softmax(A) ; mask = sigmoid(rowsum(A))
//   out_q = q + (attn @ qf) * mask ;  out_s = s * (1 + mask)

namespace {
constexpr int kB = 8, kC = 128, kN = 3136;    // N = 56*56 = 98*32
constexpr int TM = 64, TN = 32, NTH = 256;
constexpr int NUM_MT = kN / TN;               // 98
constexpr int SBUF = 16384, VBUF = 16384, PBUF = 8192;
constexpr int OFF_S  = 0;                     // 2 stages (32 KB)
constexpr int OFF_V  = 32768;                 // 3 stages (48 KB)
constexpr int OFF_P  = 81920;                 // 2 stages (16 KB)
constexpr int OFF_SC = 98304;                 // float sc[64]
constexpr int OFF_M1 = 98304 + 256;           // float m1[64]
constexpr int SMEM_BYTES = 98304 + 512;
constexpr size_t SZ = (size_t)kB * kN * kC;
}

// bf16 hi/lo scratch (written by prepass)
__device__ __align__(16) uint16_t g_qh[SZ];
__device__ __align__(16) uint16_t g_ql[SZ];
__device__ __align__(16) uint16_t g_sh[SZ];
__device__ __align__(16) uint16_t g_sl[SZ];

#define SWZ(b) ((b) ^ (((b) >> 3) & 0x70))

__device__ __forceinline__ uint32_t smem_to_u32(const void* p) {
    uint32_t a;
    asm("{ .reg .u64 t; cvta.to.shared.u64 t, %1; cvt.u32.u64 %0, t; }" : "=r"(a) : "l"(p));
    return a;
}
__device__ __forceinline__ void cp16(uint32_t dst, const void* src) {
    asm volatile("cp.async.cg.shared.global [%0], [%1], 16;" :: "r"(dst), "l"(src));
}
#define CP_COMMIT() asm volatile("cp.async.commit_group;" ::: "memory")
#define CP_WAIT0()  asm volatile("cp.async.wait_group 0;" ::: "memory")
#define CP_WAIT1()  asm volatile("cp.async.wait_group 1;" ::: "memory")

__device__ __forceinline__ void ldsm_x4(uint32_t* r, uint32_t addr) {
    asm volatile("ldmatrix.sync.aligned.m8n8.x4.shared.b16 {%0,%1,%2,%3}, [%4];"
                 : "=r"(r[0]), "=r"(r[1]), "=r"(r[2]), "=r"(r[3]) : "r"(addr));
}
__device__ __forceinline__ void ldsm_x4_t(uint32_t* r, uint32_t addr) {
    asm volatile("ldmatrix.sync.aligned.m8n8.x4.trans.shared.b16 {%0,%1,%2,%3}, [%4];"
                 : "=r"(r[0]), "=r"(r[1]), "=r"(r[2]), "=r"(r[3]) : "r"(addr));
}
__device__ __forceinline__ void stsm_x4(uint32_t addr, const uint32_t* r) {
    asm volatile("stmatrix.sync.aligned.m8n8.x4.shared.b16 [%0], {%1,%2,%3,%4};"
                 :: "r"(addr), "r"(r[0]), "r"(r[1]), "r"(r[2]), "r"(r[3]) : "memory");
}
__device__ __forceinline__ void mma_bf16(float* d, const uint32_t* a,
                                         uint32_t b0, uint32_t b1) {
    asm volatile("mma.sync.aligned.m16n8k16.row.col.f32.bf16.bf16.f32 "
                 "{%0,%1,%2,%3}, {%4,%5,%6,%7}, {%8,%9}, {%0,%1,%2,%3};"
                 : "+f"(d[0]), "+f"(d[1]), "+f"(d[2]), "+f"(d[3])
                 : "r"(a[0]), "r"(a[1]), "r"(a[2]), "r"(a[3]), "r"(b0), "r"(b1));
}
__device__ __forceinline__ void split2(float x, float y, uint32_t& hi, uint32_t& lo) {
    asm("cvt.rn.satfinite.bf16x2.f32 %0, %1, %2;" : "=r"(hi) : "f"(y), "f"(x));
    float rx = x - __uint_as_float(hi << 16);
    float ry = y - __uint_as_float(hi & 0xFFFF0000u);
    asm("cvt.rn.satfinite.bf16x2.f32 %0, %1, %2;" : "=r"(lo) : "f"(ry), "f"(rx));
}

// ---------------------------------------------------------------------------
__global__ __launch_bounds__(256)
void prepass_kernel(const float* __restrict__ q, const float* __restrict__ s)
{
    const size_t nf4 = SZ / 4;
    size_t i = (size_t)blockIdx.x * blockDim.x + threadIdx.x;
    const float* src;
    uint16_t *dh, *dl;
    size_t idx;
    if (i < nf4) { src = q; dh = g_qh; dl = g_ql; idx = i; }
    else         { src = s; dh = g_sh; dl = g_sl; idx = i - nf4; }
    float4 v = reinterpret_cast<const float4*>(src)[idx];
    uint32_t h0, l0, h1, l1;
    split2(v.x, v.y, h0, l0);
    split2(v.z, v.w, h1, l1);
    reinterpret_cast<uint2*>(dh)[idx] = make_uint2(h0, h1);
    reinterpret_cast<uint2*>(dl)[idx] = make_uint2(l0, l1);
}

// ---------------------------------------------------------------------------
// Load tile t: S -> S-stage (128 c-rows x [hi64B|lo64B]), V -> V-stage
// (4 regions [32 m][128B]: hi c0, hi c1, lo c0, lo c1).
__device__ __forceinline__ void load_tile(uint32_t sb, int tid, int b, int m0,
                                          int sS, int sV)
{
    uint32_t sbase = sb + OFF_S + (uint32_t)sS * SBUF;
    uint32_t vbase = sb + OFF_V + (uint32_t)sV * VBUF;
    #pragma unroll
    for (int i = 0; i < 4; i++) {
        int idx = tid + i * NTH;              // 0..1023
        int c = idx >> 3, j = idx & 7, jj = j & 3;
        const uint16_t* src = (j < 4 ? g_sh : g_sl)
            + ((size_t)(b * kC + c) * kN + m0 + jj * 8);
        cp16(sbase + SWZ((uint32_t)(c * 128 + ((j >> 2) << 6) + jj * 16)), src);
    }
    #pragma unroll
    for (int i = 0; i < 4; i++) {
        int idx = tid + i * NTH;              // 0..1023
        int rg = idx >> 8, m = (idx >> 3) & 31, j = idx & 7;
        const uint16_t* base = (rg < 2 ? g_qh : g_ql);
        const uint16_t* src = base + ((size_t)(b * kN + m0 + m) * kC) + (rg & 1) * 64 + j * 8;
        cp16(vbase + (uint32_t)rg * 4096 + SWZ((uint32_t)(m * 128 + j * 16)), src);
    }
}

__global__ __launch_bounds__(NTH, 2)
void fusion_mma_kernel(const float* __restrict__ q,
                       const float* __restrict__ s,
                       float* __restrict__ out)
{
    extern __shared__ char smem[];
    const uint32_t sb = smem_to_u32(smem);
    float* scbuf = reinterpret_cast<float*>(smem + OFF_SC);
    float* m1buf = reinterpret_cast<float*>(smem + OFF_M1);

    const int tid  = threadIdx.x;
    const int lane = tid & 31;
    const int wid  = tid >> 5;
    const bool isWG0 = (wid < 4);
    const int R    = (wid & 3) * 16;           // row block within the 64
    const int rowA = lane & 15;
    const int gcol = (lane >> 4) << 4;

    const int b  = blockIdx.y;
    const int n0 = blockIdx.x * TM;
    const float* __restrict__ qb  = q + (size_t)b * kN * kC;
    const float* __restrict__ sbp = s + (size_t)b * kN * kC;

    // ---- Stage Q tile (bf16 hi/lo) into S area; WG0 hoists A-fragments ----
    #pragma unroll
    for (int i = 0; i < 8; i++) {
        int idx = tid + i * NTH;               // 0..2047
        int hl = idx >> 10;
        int r = (idx >> 4) & 63, j = idx & 15;
        int ch = j >> 3, jj = j & 7;
        const uint16_t* base = hl ? g_ql : g_qh;
        const uint16_t* src = base + ((size_t)(b * kN + n0 + r) * kC) + ch * 64 + jj * 8;
        cp16(sb + (uint32_t)hl * 16384 + (uint32_t)ch * 8192
                + SWZ((uint32_t)(r * 128 + jj * 16)), src);
    }
    CP_COMMIT(); CP_WAIT0(); __syncthreads();

    // Register union: WG0 -> Q frags (qah=ubig[0..31], qal=ubig[32..63]);
    // WG1 -> O accumulators (16 quads of fp32).
    uint32_t ubig[64];
    if (isWG0) {
        #pragma unroll
        for (int k = 0; k < 8; k++) {
            uint32_t inner = SWZ((uint32_t)((R + rowA) * 128 + ((k & 3) << 5) + gcol));
            ldsm_x4(&ubig[k * 4],      sb + ((uint32_t)(k >> 2) << 13) + inner);
            ldsm_x4(&ubig[32 + k * 4], sb + 16384 + ((uint32_t)(k >> 2) << 13) + inner);
        }
    } else {
        #pragma unroll
        for (int i = 0; i < 64; i++) ubig[i] = 0;
    }
    __syncthreads();

    float raw0 = 0.f, raw1 = 0.f, es0 = 0.f, es1 = 0.f;

    // tile 0 -> S[0], V[0]
    load_tile(sb, tid, b, 0, 0, 0); CP_COMMIT();

    #pragma unroll 1
    for (int mt = 0; mt <= NUM_MT; mt++) {
        __syncthreads();                       // all prior-stage reads complete
        if (mt + 1 < NUM_MT) {
            load_tile(sb, tid, b, (mt + 1) * TN, (mt + 1) & 1, (mt + 1) % 3);
            CP_COMMIT();
            CP_WAIT1();                        // tile mt complete
        } else {
            CP_WAIT0();
        }

        if (isWG0) {
            if (mt < NUM_MT) {
                const uint32_t bbS = sb + OFF_S + (uint32_t)(mt & 1) * SBUF;
                // GEMM1: S(16x32/warp) = Q(16x128) @ Sf(128x32), 3-term
                float sacc[4][4];
                #pragma unroll
                for (int i = 0; i < 4; i++)
                    #pragma unroll
                    for (int j = 0; j < 4; j++) sacc[i][j] = 0.f;
                #pragma unroll
                for (int k = 0; k < 8; k++) {
                    uint32_t rowb = (uint32_t)((k * 16 + rowA) * 128);
                    const uint32_t* ah = &ubig[k * 4];
                    const uint32_t* al = &ubig[32 + k * 4];
                    #pragma unroll
                    for (int np = 0; np < 2; np++) {
                        uint32_t bh[4], bl[4];
                        ldsm_x4_t(bh, bbS + SWZ(rowb + ((uint32_t)np << 5) + gcol));
                        ldsm_x4_t(bl, bbS + SWZ(rowb + 64 + ((uint32_t)np << 5) + gcol));
                        mma_bf16(sacc[2*np],   ah, bh[0], bh[1]);
                        mma_bf16(sacc[2*np+1], ah, bh[2], bh[3]);
                        mma_bf16(sacc[2*np],   ah, bl[0], bl[1]);
                        mma_bf16(sacc[2*np+1], ah, bl[2], bl[3]);
                        mma_bf16(sacc[2*np],   al, bh[0], bh[1]);
                        mma_bf16(sacc[2*np+1], al, bh[2], bh[3]);
                    }
                }
                // exp + row partials; pack P into A-fragments
                uint32_t pah[2][4], pal[2][4];
                #pragma unroll
                for (int nt = 0; nt < 4; nt++) {
                    float v0 = sacc[nt][0], v1 = sacc[nt][1];
                    float v2 = sacc[nt][2], v3 = sacc[nt][3];
                    raw0 += v0 + v1;  raw1 += v2 + v3;
                    float e0 = __expf(v0), e1 = __expf(v1);
                    float e2 = __expf(v2), e3 = __expf(v3);
                    es0 += e0 + e1;   es1 += e2 + e3;
                    int kt = nt >> 1, o = (nt & 1) << 1;
                    split2(e0, e1, pah[kt][o],     pal[kt][o]);
                    split2(e2, e3, pah[kt][o + 1], pal[kt][o + 1]);
                }
                // hand P to WG1 via stmatrix (bit-exact pass-through)
                const uint32_t pbw = sb + OFF_P + (uint32_t)(mt & 1) * PBUF;
                #pragma unroll
                for (int kt = 0; kt < 2; kt++) {
                    uint32_t base = (uint32_t)((R + rowA) * 128 + (kt << 5) + gcol);
                    stsm_x4(pbw + SWZ(base),      pah[kt]);
                    stsm_x4(pbw + SWZ(base + 64), pal[kt]);
                }
            }
        } else {
            if (mt >= 1) {
                const int t = mt - 1;
                const uint32_t pbr = sb + OFF_P + (uint32_t)(t & 1) * PBUF;
                uint32_t pah[2][4], pal[2][4];
                #pragma unroll
                for (int kt = 0; kt < 2; kt++) {
                    uint32_t base = (uint32_t)((R + rowA) * 128 + (kt << 5) + gcol);
                    ldsm_x4(pah[kt], pbr + SWZ(base));
                    ldsm_x4(pal[kt], pbr + SWZ(base + 64));
                }
                const uint32_t vb0 = sb + OFF_V + (uint32_t)(t % 3) * VBUF;
                // GEMM2: O(16x128/warp) += P(16x32) @ V(32x128), 3-term
                #pragma unroll
                for (int np = 0; np < 8; np++) {
                    uint32_t vb = vb0 + (((uint32_t)np >> 2) << 12);
                    float* oA = reinterpret_cast<float*>(&ubig[(2*np)   * 4]);
                    float* oB = reinterpret_cast<float*>(&ubig[(2*np+1) * 4]);
                    #pragma unroll
                    for (int kt = 0; kt < 2; kt++) {
                        uint32_t bh[4], bl[4];
                        uint32_t off = SWZ((uint32_t)((kt * 16 + rowA) * 128
                                          + ((np & 3) << 5) + gcol));
                        ldsm_x4_t(bh, vb + off);
                        ldsm_x4_t(bl, vb + 8192 + off);
                        mma_bf16(oA, pah[kt], bh[0], bh[1]);
                        mma_bf16(oB, pah[kt], bh[2], bh[3]);
                        mma_bf16(oA, pah[kt], bl[0], bl[1]);
                        mma_bf16(oB, pah[kt], bl[2], bl[3]);
                        mma_bf16(oA, pal[kt], bh[0], bh[1]);
                        mma_bf16(oB, pal[kt], bh[2], bh[3]);
                    }
                }
            }
        }
    }

    // ---- WG0: finalize row stats -> smem ----
    if (isWG0) {
        #pragma unroll
        for (int off = 1; off < 4; off <<= 1) {
            raw0 += __shfl_xor_sync(0xffffffffu, raw0, off);
            raw1 += __shfl_xor_sync(0xffffffffu, raw1, off);
            es0  += __shfl_xor_sync(0xffffffffu, es0,  off);
            es1  += __shfl_xor_sync(0xffffffffu, es1,  off);
        }
        if ((lane & 3) == 0) {
            float mask0 = 1.f / (1.f + __expf(-raw0));
            float mask1 = 1.f / (1.f + __expf(-raw1));
            int r = R + (lane >> 2);
            scbuf[r]     = mask0 / es0;
            scbuf[r + 8] = mask1 / es1;
            m1buf[r]     = 1.f + mask0;
            m1buf[r + 8] = 1.f + mask1;
        }
    }
    __syncthreads();

    // ---- WG1: query output out_q = q + O * scale ----
    if (!isWG0) {
        float* outq = out + (size_t)b * kN * kC;
        int r0 = R + (lane >> 2);
        int gr0 = n0 + r0, gr1 = gr0 + 8;
        float sc0 = scbuf[r0], sc1 = scbuf[r0 + 8];
        #pragma unroll
        for (int nt = 0; nt < 16; nt++) {
            const float* o4 = reinterpret_cast<const float*>(&ubig[nt * 4]);
            int c = nt * 8 + (lane & 3) * 2;
            float2 q0 = *reinterpret_cast<const float2*>(qb + (size_t)gr0 * kC + c);
            float2 q1 = *reinterpret_cast<const float2*>(qb + (size_t)gr1 * kC + c);
            float2 o0, o1;
            o0.x = fmaf(o4[0], sc0, q0.x);
            o0.y = fmaf(o4[1], sc0, q0.y);
            o1.x = fmaf(o4[2], sc1, q1.x);
            o1.y = fmaf(o4[3], sc1, q1.y);
            *reinterpret_cast<float2*>(outq + (size_t)gr0 * kC + c) = o0;
            *reinterpret_cast<float2*>(outq + (size_t)gr1 * kC + c) = o1;
        }
    }

    // ---- all warps: support output out_s = s * (1 + mask[row]) ----
    {
        float* outs = out + (size_t)kB * kN * kC + (size_t)b * kN * kC;
        #pragma unroll
        for (int i = 0; i < 8; i++) {
            int idx = tid + i * NTH;           // 0..2047 float4
            int row = idx >> 5, c4 = (idx & 31) << 2;
            float m1 = m1buf[row];
            float4 v = *reinterpret_cast<const float4*>(sbp + (size_t)(n0 + row) * kC + c4);
            v.x *= m1; v.y *= m1; v.z *= m1; v.w *= m1;
            *reinterpret_cast<float4*>(outs + (size_t)(n0 + row) * kC + c4) = v;
        }
    }
}

extern "C" void kernel_launch(void* const* d_in, const int* in_sizes, int n_in,
                              void* d_out, int out_size)
{
    const float* q = (const float*)d_in[0];   // query_feature  [8,128,56,56]
    const float* s = (const float*)d_in[1];   // support_feature[8,128,56,56]
    float* out = (float*)d_out;               // [query_out | support_out]

    const size_t nf4 = SZ / 4;
    int pre_blocks = (int)((2 * nf4 + 255) / 256);
    prepass_kernel<<<pre_blocks, 256>>>(q, s);

    cudaFuncSetAttribute((const void*)fusion_mma_kernel,
                         cudaFuncAttributeMaxDynamicSharedMemorySize, SMEM_BYTES);
    dim3 grid(kN / TM, kB);                   // 49 x 8 = 392 CTAs
    fusion_mma_kernel<<<grid, NTH, SMEM_BYTES>>>(q, s, out);
}

// round 17
// speedup vs baseline: 1.0057x; 1.0057x over previous
#include <cuda_runtime.h>
#include <cstdint>

// FusionFeature_Layer on GB300 — emulated-fp32 flash attention on mma.sync
// (bf16 hi/lo 3-term split), bf16 prepass + cp.async pipelined tiles.
// R17: symmetric 8-warp CTA (4 row-blocks x 2 column-halves), 256 threads,
// <=128 regs -> 2 CTAs/SM, 4 MMA warps per SMSP. P exchanged via
// stmatrix/ldmatrix (bit-exact). Q fragments reloaded from smem per tile.
//
//   qf[b,n,c] = query.flat [b*N*C + n*C + c]
//   sf[b,c,m] = support.flat[b*C*N + c*N + m]
//   A = qf @ sf ; attn = softmax(A) ; mask = sigmoid(rowsum(A))
//   out_q = q + (attn @ qf) * mask ;  out_s = s * (1 + mask)

namespace {
constexpr int kB = 8, kC = 128, kN = 3136;    // N = 56*56 = 98*32
constexpr int TM = 64, TN = 32, NTH = 256;
constexpr int NUM_MT = kN / TN;               // 98
// smem layout (per CTA), all regions swizzle-friendly 128B pitch
constexpr int OFF_Q    = 0;                   // QH0,QH1,QL0,QL1: 4 x 8K = 32K
constexpr int OFF_S    = 32768;               // 2 stages x 16K  ([128c][hi64|lo64])
constexpr int OFF_V    = 65536;               // 2 stages x 16K  (4 regions [32m][128B])
constexpr int OFF_P    = 98304;               // 8K ([64r][hi64|lo64])
constexpr int OFF_PRAW = 106496;              // float[2][64]
constexpr int OFF_PEXP = 106496 + 512;        // float[2][64]
constexpr int OFF_SC   = 106496 + 1024;       // float[64]
constexpr int OFF_M1   = 106496 + 1280;       // float[64]
constexpr int SMEM_BYTES = 106496 + 1536;     // 108032 -> 2 CTAs = 216K <= 228K
constexpr size_t SZ = (size_t)kB * kN * kC;
}

// bf16 hi/lo scratch (written by prepass)
__device__ __align__(16) uint16_t g_qh[SZ];
__device__ __align__(16) uint16_t g_ql[SZ];
__device__ __align__(16) uint16_t g_sh[SZ];
__device__ __align__(16) uint16_t g_sl[SZ];

#define SWZ(b) ((b) ^ (((b) >> 3) & 0x70))

__device__ __forceinline__ uint32_t smem_to_u32(const void* p) {
    uint32_t a;
    asm("{ .reg .u64 t; cvta.to.shared.u64 t, %1; cvt.u32.u64 %0, t; }" : "=r"(a) : "l"(p));
    return a;
}
__device__ __forceinline__ void cp16(uint32_t dst, const void* src) {
    asm volatile("cp.async.cg.shared.global [%0], [%1], 16;" :: "r"(dst), "l"(src));
}
#define CP_COMMIT() asm volatile("cp.async.commit_group;" ::: "memory")
#define CP_WAIT0()  asm volatile("cp.async.wait_group 0;" ::: "memory")

__device__ __forceinline__ void ldsm_x4(uint32_t* r, uint32_t addr) {
    asm volatile("ldmatrix.sync.aligned.m8n8.x4.shared.b16 {%0,%1,%2,%3}, [%4];"
                 : "=r"(r[0]), "=r"(r[1]), "=r"(r[2]), "=r"(r[3]) : "r"(addr));
}
__device__ __forceinline__ void ldsm_x4_t(uint32_t* r, uint32_t addr) {
    asm volatile("ldmatrix.sync.aligned.m8n8.x4.trans.shared.b16 {%0,%1,%2,%3}, [%4];"
                 : "=r"(r[0]), "=r"(r[1]), "=r"(r[2]), "=r"(r[3]) : "r"(addr));
}
__device__ __forceinline__ void stsm_x4(uint32_t addr, const uint32_t* r) {
    asm volatile("stmatrix.sync.aligned.m8n8.x4.shared.b16 [%0], {%1,%2,%3,%4};"
                 :: "r"(addr), "r"(r[0]), "r"(r[1]), "r"(r[2]), "r"(r[3]) : "memory");
}
__device__ __forceinline__ void mma_bf16(float* d, const uint32_t* a,
                                         uint32_t b0, uint32_t b1) {
    asm volatile("mma.sync.aligned.m16n8k16.row.col.f32.bf16.bf16.f32 "
                 "{%0,%1,%2,%3}, {%4,%5,%6,%7}, {%8,%9}, {%0,%1,%2,%3};"
                 : "+f"(d[0]), "+f"(d[1]), "+f"(d[2]), "+f"(d[3])
                 : "r"(a[0]), "r"(a[1]), "r"(a[2]), "r"(a[3]), "r"(b0), "r"(b1));
}
__device__ __forceinline__ void split2(float x, float y, uint32_t& hi, uint32_t& lo) {
    asm("cvt.rn.satfinite.bf16x2.f32 %0, %1, %2;" : "=r"(hi) : "f"(y), "f"(x));
    float rx = x - __uint_as_float(hi << 16);
    float ry = y - __uint_as_float(hi & 0xFFFF0000u);
    asm("cvt.rn.satfinite.bf16x2.f32 %0, %1, %2;" : "=r"(lo) : "f"(ry), "f"(rx));
}

// ---------------------------------------------------------------------------
__global__ __launch_bounds__(256)
void prepass_kernel(const float* __restrict__ q, const float* __restrict__ s)
{
    const size_t nf4 = SZ / 4;
    size_t i = (size_t)blockIdx.x * blockDim.x + threadIdx.x;
    const float* src;
    uint16_t *dh, *dl;
    size_t idx;
    if (i < nf4) { src = q; dh = g_qh; dl = g_ql; idx = i; }
    else         { src = s; dh = g_sh; dl = g_sl; idx = i - nf4; }
    float4 v = reinterpret_cast<const float4*>(src)[idx];
    uint32_t h0, l0, h1, l1;
    split2(v.x, v.y, h0, l0);
    split2(v.z, v.w, h1, l1);
    reinterpret_cast<uint2*>(dh)[idx] = make_uint2(h0, h1);
    reinterpret_cast<uint2*>(dl)[idx] = make_uint2(l0, l1);
}

// ---------------------------------------------------------------------------
// Tile loader: S -> [128 c][hi64B|lo64B]; V -> 4 regions [32 m][128B]
// (hi c0-63, hi c64-127, lo c0-63, lo c64-127). 8 cp16 per thread.
__device__ __forceinline__ void load_tile(uint32_t sb, int tid, int b, int m0, int st)
{
    uint32_t sbase = sb + OFF_S + (uint32_t)st * 16384;
    uint32_t vbase = sb + OFF_V + (uint32_t)st * 16384;
    #pragma unroll
    for (int i = 0; i < 4; i++) {
        int idx = tid + i * NTH;              // 0..1023
        int c = idx >> 3, j = idx & 7, jj = j & 3;
        const uint16_t* src = (j < 4 ? g_sh : g_sl)
            + ((size_t)(b * kC + c) * kN + m0 + jj * 8);
        cp16(sbase + SWZ((uint32_t)(c * 128 + ((j >> 2) << 6) + jj * 16)), src);
    }
    #pragma unroll
    for (int i = 0; i < 4; i++) {
        int idx = tid + i * NTH;              // 0..1023
        int rg = idx >> 8, m = (idx >> 3) & 31, j = idx & 7;
        const uint16_t* base = (rg < 2 ? g_qh : g_ql);
        const uint16_t* src = base + ((size_t)(b * kN + m0 + m) * kC) + (rg & 1) * 64 + j * 8;
        cp16(vbase + (uint32_t)rg * 4096 + SWZ((uint32_t)(m * 128 + j * 16)), src);
    }
}

__global__ __launch_bounds__(NTH, 2)
void fusion_mma_kernel(const float* __restrict__ q,
                       const float* __restrict__ s,
                       float* __restrict__ out)
{
    extern __shared__ char smem[];
    const uint32_t sb = smem_to_u32(smem);
    float* praw  = reinterpret_cast<float*>(smem + OFF_PRAW);
    float* pexp  = reinterpret_cast<float*>(smem + OFF_PEXP);
    float* scbuf = reinterpret_cast<float*>(smem + OFF_SC);
    float* m1buf = reinterpret_cast<float*>(smem + OFF_M1);

    const int tid  = threadIdx.x;
    const int lane = tid & 31;
    const int wid  = tid >> 5;
    const int rw   = wid & 3;                  // row block (16 rows)
    const int ch   = wid >> 2;                 // column half
    const int R    = rw * 16;
    const int rowA = lane & 15;
    const int gcol = (lane >> 4) << 4;

    const int b  = blockIdx.y;
    const int n0 = blockIdx.x * TM;
    const float* __restrict__ qb  = q + (size_t)b * kN * kC;
    const float* __restrict__ sbp = s + (size_t)b * kN * kC;

    // ---- Stage Q tile (bf16 hi/lo) into resident smem regions ----
    #pragma unroll
    for (int i = 0; i < 8; i++) {
        int idx = tid + i * NTH;               // 0..2047
        int hl = idx >> 10;
        int r = (idx >> 4) & 63, j = idx & 15;
        int c2 = j >> 3, jj = j & 7;
        const uint16_t* base = hl ? g_ql : g_qh;
        const uint16_t* src = base + ((size_t)(b * kN + n0 + r) * kC) + c2 * 64 + jj * 8;
        cp16(sb + OFF_Q + (uint32_t)hl * 16384 + (uint32_t)c2 * 8192
                + SWZ((uint32_t)(r * 128 + jj * 16)), src);
    }
    CP_COMMIT(); CP_WAIT0(); __syncthreads();

    float oacc[8][4];
    #pragma unroll
    for (int i = 0; i < 8; i++)
        #pragma unroll
        for (int j = 0; j < 4; j++) oacc[i][j] = 0.f;
    float raw0 = 0.f, raw1 = 0.f, es0 = 0.f, es1 = 0.f;

    load_tile(sb, tid, b, 0, 0); CP_COMMIT();

    #pragma unroll 1
    for (int mt = 0; mt < NUM_MT; mt++) {
        CP_WAIT0();
        __syncthreads();                       // tile mt visible; prev reads done
        if (mt + 1 < NUM_MT) { load_tile(sb, tid, b, (mt + 1) * TN, (mt + 1) & 1); CP_COMMIT(); }

        const uint32_t bbS = sb + OFF_S + (uint32_t)(mt & 1) * 16384;
        const uint32_t bbV = sb + OFF_V + (uint32_t)(mt & 1) * 16384;

        // ---- GEMM1: S(16x16/warp) = Q(16x128) @ Sf(128x16-half), 3-term ----
        float sacc[2][4];
        #pragma unroll
        for (int i = 0; i < 2; i++)
            #pragma unroll
            for (int j = 0; j < 4; j++) sacc[i][j] = 0.f;
        #pragma unroll
        for (int k = 0; k < 8; k++) {
            uint32_t ainner = SWZ((uint32_t)((R + rowA) * 128 + ((k & 3) << 5) + gcol));
            uint32_t qh[4], ql[4], bh[4], bl[4];
            ldsm_x4(qh, sb + OFF_Q + ((uint32_t)(k >> 2) << 13) + ainner);
            ldsm_x4(ql, sb + OFF_Q + 16384 + ((uint32_t)(k >> 2) << 13) + ainner);
            uint32_t rowb = (uint32_t)((k * 16 + rowA) * 128);
            ldsm_x4_t(bh, bbS + SWZ(rowb + ((uint32_t)ch << 5) + gcol));
            ldsm_x4_t(bl, bbS + SWZ(rowb + 64 + ((uint32_t)ch << 5) + gcol));
            mma_bf16(sacc[0], qh, bh[0], bh[1]);
            mma_bf16(sacc[1], qh, bh[2], bh[3]);
            mma_bf16(sacc[0], qh, bl[0], bl[1]);
            mma_bf16(sacc[1], qh, bl[2], bl[3]);
            mma_bf16(sacc[0], ql, bh[0], bh[1]);
            mma_bf16(sacc[1], ql, bh[2], bh[3]);
        }

        // ---- exp + row partials; pack P A-fragments; stmatrix to P buf ----
        {
            uint32_t pah[4], pal[4];
            #pragma unroll
            for (int nt = 0; nt < 2; nt++) {
                float v0 = sacc[nt][0], v1 = sacc[nt][1];
                float v2 = sacc[nt][2], v3 = sacc[nt][3];
                raw0 += v0 + v1;  raw1 += v2 + v3;
                float e0 = __expf(v0), e1 = __expf(v1);
                float e2 = __expf(v2), e3 = __expf(v3);
                es0 += e0 + e1;   es1 += e2 + e3;
                int o = nt << 1;
                split2(e0, e1, pah[o],     pal[o]);
                split2(e2, e3, pah[o + 1], pal[o + 1]);
            }
            uint32_t base = (uint32_t)((R + rowA) * 128 + (ch << 5) + gcol);
            stsm_x4(sb + OFF_P + SWZ(base),      pah);
            stsm_x4(sb + OFF_P + SWZ(base + 64), pal);
        }
        __syncthreads();                       // P visible to the warp pair

        // ---- GEMM2: O(16x64/warp) += P(16x32) @ V(32x64-half), 3-term ----
        {
            uint32_t pah2[2][4], pal2[2][4];
            #pragma unroll
            for (int kt = 0; kt < 2; kt++) {
                uint32_t base = (uint32_t)((R + rowA) * 128 + (kt << 5) + gcol);
                ldsm_x4(pah2[kt], sb + OFF_P + SWZ(base));
                ldsm_x4(pal2[kt], sb + OFF_P + SWZ(base + 64));
            }
            uint32_t vh = bbV + (uint32_t)ch * 4096;
            uint32_t vl = vh + 8192;
            #pragma unroll
            for (int npq = 0; npq < 4; npq++) {
                #pragma unroll
                for (int kt = 0; kt < 2; kt++) {
                    uint32_t off = SWZ((uint32_t)((kt * 16 + rowA) * 128
                                      + (npq << 5) + gcol));
                    uint32_t bh[4], bl[4];
                    ldsm_x4_t(bh, vh + off);
                    ldsm_x4_t(bl, vl + off);
                    float* oA = oacc[2 * npq];
                    float* oB = oacc[2 * npq + 1];
                    mma_bf16(oA, pah2[kt], bh[0], bh[1]);
                    mma_bf16(oB, pah2[kt], bh[2], bh[3]);
                    mma_bf16(oA, pah2[kt], bl[0], bl[1]);
                    mma_bf16(oB, pah2[kt], bl[2], bl[3]);
                    mma_bf16(oA, pal2[kt], bh[0], bh[1]);
                    mma_bf16(oB, pal2[kt], bh[2], bh[3]);
                }
            }
        }
    }

    // ---- row stats: quad-reduce, combine the two n-halves via smem ----
    #pragma unroll
    for (int off = 1; off < 4; off <<= 1) {
        raw0 += __shfl_xor_sync(0xffffffffu, raw0, off);
        raw1 += __shfl_xor_sync(0xffffffffu, raw1, off);
        es0  += __shfl_xor_sync(0xffffffffu, es0,  off);
        es1  += __shfl_xor_sync(0xffffffffu, es1,  off);
    }
    if ((lane & 3) == 0) {
        int r = R + (lane >> 2);
        praw[ch * 64 + r]     = raw0;  pexp[ch * 64 + r]     = es0;
        praw[ch * 64 + r + 8] = raw1;  pexp[ch * 64 + r + 8] = es1;
    }
    __syncthreads();
    if (tid < 64) {
        float rs = praw[tid] + praw[64 + tid];
        float es = pexp[tid] + pexp[64 + tid];
        float mask = 1.f / (1.f + __expf(-rs));
        scbuf[tid] = mask / es;
        m1buf[tid] = 1.f + mask;
    }
    __syncthreads();

    // ---- query output: out_q = q + O * scale (warp writes its 16x64) ----
    {
        float* outq = out + (size_t)b * kN * kC;
        int r0 = R + (lane >> 2);
        int gr0 = n0 + r0, gr1 = gr0 + 8;
        float sc0 = scbuf[r0], sc1 = scbuf[r0 + 8];
        #pragma unroll
        for (int nt = 0; nt < 8; nt++) {
            int c = ch * 64 + nt * 8 + (lane & 3) * 2;
            float2 q0 = *reinterpret_cast<const float2*>(qb + (size_t)gr0 * kC + c);
            float2 q1 = *reinterpret_cast<const float2*>(qb + (size_t)gr1 * kC + c);
            float2 o0, o1;
            o0.x = fmaf(oacc[nt][0], sc0, q0.x);
            o0.y = fmaf(oacc[nt][1], sc0, q0.y);
            o1.x = fmaf(oacc[nt][2], sc1, q1.x);
            o1.y = fmaf(oacc[nt][3], sc1, q1.y);
            *reinterpret_cast<float2*>(outq + (size_t)gr0 * kC + c) = o0;
            *reinterpret_cast<float2*>(outq + (size_t)gr1 * kC + c) = o1;
        }
    }

    // ---- support output: out_s = s * (1 + mask[row]) ----
    {
        float* outs = out + (size_t)kB * kN * kC + (size_t)b * kN * kC;
        #pragma unroll
        for (int i = 0; i < 8; i++) {
            int idx = tid + i * NTH;           // 0..2047 float4
            int row = idx >> 5, c4 = (idx & 31) << 2;
            float m1 = m1buf[row];
            float4 v = *reinterpret_cast<const float4*>(sbp + (size_t)(n0 + row) * kC + c4);
            v.x *= m1; v.y *= m1; v.z *= m1; v.w *= m1;
            *reinterpret_cast<float4*>(outs + (size_t)(n0 + row) * kC + c4) = v;
        }
    }
}

extern "C" void kernel_launch(void* const* d_in, const int* in_sizes, int n_in,
                              void* d_out, int out_size)
{
    const float* q = (const float*)d_in[0];   // query_feature  [8,128,56,56]
    const float* s = (const float*)d_in[1];   // support_feature[8,128,56,56]
    float* out = (float*)d_out;               // [query_out | support_out]

    const size_t nf4 = SZ / 4;
    int pre_blocks = (int)((2 * nf4 + 255) / 256);
    prepass_kernel<<<pre_blocks, 256>>>(q, s);

    cudaFuncSetAttribute((const void*)fusion_mma_kernel,
                         cudaFuncAttributeMaxDynamicSharedMemorySize, SMEM_BYTES);
    cudaFuncSetAttribute((const void*)fusion_mma_kernel,
                         cudaFuncAttributePreferredSharedMemoryCarveout, 100);
    dim3 grid(kN / TM, kB);                   // 49 x 8 = 392 CTAs
    fusion_mma_kernel<<<grid, NTH, SMEM_BYTES>>>(q, s, out);
}